// round 13
// baseline (speedup 1.0000x reference)
#include <cuda_runtime.h>
#include <cstdint>

// Problem constants (fixed by setup_inputs)
#define BB    4
#define NP    2000
#define NG    100
#define MH    1024
#define MW    1024
#define PCAP  66
#define NCAP  134
#define TROIS 200
#define MS1   28
#define MS2   28
#define MPIX  (MS1*MS2)

#define CHUNKS   16           // flag blocks per image
#define CHUNK_SZ (NP/CHUNKS)  // 125 proposals per block
#define TPP      8            // threads per proposal
#define FBLK     1024         // 8 * 128 slots (125 used)
#define SEG      200          // selection segments
#define SEG_SZ   (NP/SEG)     // 10 proposals per segment

// Output layout (flattened tuple, all float32)
#define OFF_CLS   (BB*TROIS*4)
#define OFF_DEL   (BB*TROIS*4 + BB*TROIS)
#define OFF_MASK  (BB*TROIS*4 + BB*TROIS + BB*TROIS*4)

// Inter-kernel scratch
__device__ int           d_mask_kind;          // 0=uint8, 1=int32, 2=float32
__device__ unsigned char d_flag[BB][NP];       // 0 none, 1 pos, 2 neg
__device__ int           d_done[BB];           // finisher election (reset after use)
__device__ int           d_num_pos[BB];
__device__ int           d_gt_assign[BB][PCAP];
__device__ float         d_pos_roi[BB][PCAP][4];

// IEEE-exact IoU matching XLA op order (immune to --use_fast_math).
__device__ __forceinline__ float iou_pair(float py1,float px1,float py2,float px2,float a1,
                                          float gy1,float gx1,float gy2,float gx2,float a2){
    float y1 = fmaxf(py1, gy1);
    float x1 = fmaxf(px1, gx1);
    float y2 = fminf(py2, gy2);
    float x2 = fminf(px2, gx2);
    float dy = fmaxf(__fsub_rn(y2, y1), 0.0f);
    float dx = fmaxf(__fsub_rn(x2, x1), 0.0f);
    float inter = __fmul_rn(dy, dx);
    float uni = __fsub_rn(__fadd_rn(a1, a2), inter);
    return __fdiv_rn(inter, uni > 0.0f ? uni : 1.0f);
}

__device__ __forceinline__ float box_area(float y1, float x1, float y2, float x2) {
    return __fmul_rn(__fsub_rn(y2, y1), __fsub_rn(x2, x1));
}

// ---------------------------------------------------------------------------
// Kernel 1: flags + (last block per image) selection & non-mask outputs.
// blocks 0..BB*CHUNKS-1: proposal flags, 8 threads/proposal; the LAST block to
// finish each image's flags runs the whole per-image selection (block-uniform
// branch -> interior __syncthreads legal; deadlock-free; deterministic).
// block BB*CHUNKS: dtype probe.
// ---------------------------------------------------------------------------
__global__ void __launch_bounds__(FBLK) k_flags_select(
        const float* __restrict__ props,
        const int*   __restrict__ gtc,
        const float* __restrict__ gtb,
        const unsigned int* __restrict__ mask_words,
        float* __restrict__ out) {
    if (blockIdx.x == BB * CHUNKS) {
        __shared__ int s_flags;
        if (threadIdx.x == 0) s_flags = 0;
        __syncthreads();
        unsigned int w = mask_words[threadIdx.x];
        int f = 0;
        if (w == 0x3F800000u) f |= 1;
        else if (w != 0u && w != 1u) f |= 2;
        for (int o = 16; o > 0; o >>= 1) f |= __shfl_xor_sync(0xFFFFFFFFu, f, o);
        if ((threadIdx.x & 31) == 0 && f) atomicOr(&s_flags, f);
        __syncthreads();
        if (threadIdx.x == 0) {
            int fl = s_flags;
            d_mask_kind = (fl & 1) ? 2 : ((fl & 2) ? 0 : 1);
        }
        return;
    }

    int b     = blockIdx.x / CHUNKS;
    int chunk = blockIdx.x % CHUNKS;
    int t     = threadIdx.x;

    // ---- flags phase: compacted valid-GT lists (SoA) ----
    __shared__ float s_gy1[NG], s_gx1[NG], s_gy2[NG], s_gx2[NG], s_ga2[NG];
    __shared__ float s_cy1[NG], s_cx1[NG], s_cy2[NG], s_cx2[NG], s_ca2[NG];
    __shared__ int   s_nok, s_ncrowd, s_last;

    if (t == 0) { s_nok = 0; s_ncrowd = 0; }
    __syncthreads();
    if (t < NG) {
        int g = t;
        const float* gp = gtb + ((size_t)b * NG + g) * 4;
        float y1 = gp[0], x1 = gp[1], y2 = gp[2], x2 = gp[3];
        bool valid = (y1 != 0.0f) || (x1 != 0.0f) || (y2 != 0.0f) || (x2 != 0.0f);
        int cls = gtc[(size_t)b * NG + g];
        if (valid && cls > 0) {
            int s = atomicAdd(&s_nok, 1);
            s_gy1[s] = y1; s_gx1[s] = x1; s_gy2[s] = y2; s_gx2[s] = x2;
            s_ga2[s] = box_area(y1, x1, y2, x2);
        } else if (valid && cls < 0) {
            int s = atomicAdd(&s_ncrowd, 1);
            s_cy1[s] = y1; s_cx1[s] = x1; s_cy2[s] = y2; s_cx2[s] = x2;
            s_ca2[s] = box_area(y1, x1, y2, x2);
        }
    }
    __syncthreads();

    {
        int idx  = t / TPP;        // proposal within chunk (0..127)
        int part = t % TPP;
        bool active = idx < CHUNK_SZ;
        int n = chunk * CHUNK_SZ + idx;

        float py1 = 0, px1 = 0, py2 = 0, px2 = 0, a1 = 0;
        bool pv = false;
        if (active) {
            const float* pp = props + ((size_t)b * NP + n) * 4;
            py1 = pp[0]; px1 = pp[1]; py2 = pp[2]; px2 = pp[3];
            pv = (py1 != 0.0f) || (px1 != 0.0f) || (py2 != 0.0f) || (px2 != 0.0f);
            a1 = box_area(py1, px1, py2, px2);
        }

        int pos = 0, crowd_hit = 0;
        if (active && pv) {
            int nok = s_nok;
            for (int s = part; s < nok; s += TPP) {
                float y1 = fmaxf(py1, s_gy1[s]);
                float x1 = fmaxf(px1, s_gx1[s]);
                float y2 = fminf(py2, s_gy2[s]);
                float x2 = fminf(px2, s_gx2[s]);
                float inter = __fmul_rn(fmaxf(__fsub_rn(y2, y1), 0.0f),
                                        fmaxf(__fsub_rn(x2, x1), 0.0f));
                float uni = __fsub_rn(__fadd_rn(a1, s_ga2[s]), inter);
                float denom = uni > 0.0f ? uni : 1.0f;
                float half_u = __fmul_rn(0.5f, denom);     // exact
                if (inter >= half_u) { pos = 1; }
                else if (inter >= __fmul_rn(half_u, 0.999999f)) {
                    if (__fdiv_rn(inter, denom) >= 0.5f) pos = 1;   // half-ulp band
                }
            }
            int ncr = s_ncrowd;
            for (int s = part; s < ncr; s += TPP) {   // (empty for this dataset)
                float y1 = fmaxf(py1, s_cy1[s]);
                float x1 = fmaxf(px1, s_cx1[s]);
                float y2 = fminf(py2, s_cy2[s]);
                float x2 = fminf(px2, s_cx2[s]);
                float inter = __fmul_rn(fmaxf(__fsub_rn(y2, y1), 0.0f),
                                        fmaxf(__fsub_rn(x2, x1), 0.0f));
                float uni = __fsub_rn(__fadd_rn(a1, s_ca2[s]), inter);
                float denom = uni > 0.0f ? uni : 1.0f;
                if (inter >= __fmul_rn(denom, 0.001001f)) crowd_hit = 1;
                else if (inter >= __fmul_rn(denom, 0.000999f)) {
                    if (__fdiv_rn(inter, denom) >= 0.001f) crowd_hit = 1;
                }
            }
        }
        // OR-combine across the 8 partitions (warp-uniform shuffles)
        #pragma unroll
        for (int o = TPP/2; o > 0; o >>= 1) {
            pos       |= __shfl_down_sync(0xFFFFFFFFu, pos, o, TPP);
            crowd_hit |= __shfl_down_sync(0xFFFFFFFFu, crowd_hit, o, TPP);
        }
        if (part == 0 && active) {
            unsigned char f = 0;
            if (pv) {
                if (pos) f = 1;
                else if (!crowd_hit) f = 2;
            }
            d_flag[b][n] = f;
        }
    }

    // ---- finisher election (block-uniform) ----
    __syncthreads();
    if (t == 0) {
        __threadfence();
        s_last = (atomicAdd(&d_done[b], 1) == CHUNKS - 1) ? 1 : 0;
    }
    __syncthreads();
    if (!s_last) return;
    __threadfence();   // acquire: other blocks' d_flag writes are visible

    // =========== selection + rois/class/deltas (one block per image) ===========
    __shared__ float s_g[NG][4];
    __shared__ float s_area[NG];
    __shared__ int   s_cls[NG];
    __shared__ unsigned char s_ok[NG];
    __shared__ unsigned char s_flag[NP];
    __shared__ short s_poff[SEG];
    __shared__ short s_noff[SEG];
    __shared__ int   s_np, s_nn;
    __shared__ short s_pos_idx[PCAP];
    __shared__ short s_neg_idx[NCAP];
    __shared__ int   s_ga[PCAP];

    if (t < NG) {
        int g = t;
        const float* gp = gtb + ((size_t)b * NG + g) * 4;
        float y1 = gp[0], x1 = gp[1], y2 = gp[2], x2 = gp[3];
        s_g[g][0] = y1; s_g[g][1] = x1; s_g[g][2] = y2; s_g[g][3] = x2;
        bool valid = (y1 != 0.0f) || (x1 != 0.0f) || (y2 != 0.0f) || (x2 != 0.0f);
        int cls = gtc[(size_t)b * NG + g];
        s_cls[g]  = cls;
        s_ok[g]   = (valid && cls > 0) ? 1 : 0;
        s_area[g] = box_area(y1, x1, y2, x2);
    }
    for (int n = t; n < NP; n += FBLK)
        s_flag[n] = d_flag[b][n];
    __syncthreads();

    // Phase 1: per-segment pos/neg counts
    if (t < SEG) {
        int pc = 0, nc = 0;
        #pragma unroll
        for (int k = 0; k < SEG_SZ; k++) {
            unsigned char f = s_flag[t * SEG_SZ + k];
            pc += (f == 1);
            nc += (f == 2);
        }
        s_poff[t] = (short)pc;
        s_noff[t] = (short)nc;
    }
    __syncthreads();
    // Phase 2: exclusive prefix (thread 0) + counter reset for next replay
    if (t == 0) {
        int rp = 0, rn = 0;
        for (int s = 0; s < SEG; s++) {
            int c = s_poff[s]; s_poff[s] = (short)rp; rp += c;
            c = s_noff[s];     s_noff[s] = (short)rn; rn += c;
        }
        int np = rp < PCAP ? rp : PCAP;
        int nn = rn < NCAP ? rn : NCAP;
        // XLA lowers x/0.33f to x * rn(1/0.33f): 66*3.03030300140381f = 200.0
        float recip = __fdiv_rn(1.0f, 0.33f);
        int neg_target = (int)__fmul_rn((float)np, recip) - np;
        if (neg_target < 0) neg_target = 0;
        s_np = np;
        s_nn = (nn < neg_target) ? nn : neg_target;
        d_num_pos[b] = np;
        d_done[b] = 0;          // reset for next graph replay
    }
    __syncthreads();
    // Phase 3: segments emit ordered indices at their exclusive offsets
    if (t < SEG) {
        int rp = s_poff[t], rn = s_noff[t];
        #pragma unroll
        for (int k = 0; k < SEG_SZ; k++) {
            int n = t * SEG_SZ + k;
            unsigned char f = s_flag[n];
            if (f == 1) { if (rp < PCAP) s_pos_idx[rp] = (short)n; rp++; }
            else if (f == 2) { if (rn < NCAP) s_neg_idx[rn] = (short)n; rn++; }
        }
    }
    __syncthreads();

    int np = s_np;
    int nn = s_nn;

    // Phase 4: GT argmax, 4 threads per positive ROI; all threads execute
    // (warp-uniform shuffles), roi>=np carry dummies.
    {
        int roi  = t >> 2;
        int part = t & 3;
        float best_v = -2.0f;
        int   best_g = 0;
        if (roi < np) {
            int n = s_pos_idx[roi];
            const float* pp = props + ((size_t)b * NP + n) * 4;
            float r0 = pp[0], r1 = pp[1], r2 = pp[2], r3 = pp[3];
            float a1 = box_area(r0, r1, r2, r3);
            int g0 = part * (NG / 4);
            for (int g = g0; g < g0 + NG / 4; g++) {
                float v = s_ok[g] ? iou_pair(r0, r1, r2, r3, a1,
                                             s_g[g][0], s_g[g][1], s_g[g][2], s_g[g][3],
                                             s_area[g])
                                  : -1.0f;
                if (v > best_v) { best_v = v; best_g = g; }
            }
        }
        // (v desc, g asc) reduce => first-max semantics
        #pragma unroll
        for (int o = 2; o > 0; o >>= 1) {
            float ov = __shfl_down_sync(0xFFFFFFFFu, best_v, o, 4);
            int   og = __shfl_down_sync(0xFFFFFFFFu, best_g, o, 4);
            if (ov > best_v || (ov == best_v && og < best_g)) { best_v = ov; best_g = og; }
        }
        if (part == 0 && roi < PCAP) s_ga[roi] = (roi < np) ? best_g : 0;
    }
    __syncthreads();

    float* rois_out = out + (size_t)b * TROIS * 4;
    float* cls_out  = out + OFF_CLS + (size_t)b * TROIS;
    float* del_out  = out + OFF_DEL + (size_t)b * TROIS * 4;

    if (t < PCAP) {
        float r0 = 0, r1 = 0, r2 = 0, r3 = 0;
        float c = 0, d0 = 0, d1 = 0, d2 = 0, d3 = 0;
        int ga = s_ga[t];
        if (t < np) {
            int n = s_pos_idx[t];
            const float* pp = props + ((size_t)b * NP + n) * 4;
            r0 = pp[0]; r1 = pp[1]; r2 = pp[2]; r3 = pp[3];
            float gy1 = s_g[ga][0], gx1 = s_g[ga][1], gy2 = s_g[ga][2], gx2 = s_g[ga][3];
            float h  = __fsub_rn(r2, r0);
            float w  = __fsub_rn(r3, r1);
            float gh = __fsub_rn(gy2, gy1);
            float gw = __fsub_rn(gx2, gx1);
            float cy  = __fadd_rn(r0,  __fmul_rn(0.5f, h));
            float cx  = __fadd_rn(r1,  __fmul_rn(0.5f, w));
            float gcy = __fadd_rn(gy1, __fmul_rn(0.5f, gh));
            float gcx = __fadd_rn(gx1, __fmul_rn(0.5f, gw));
            d0 = __fdiv_rn(__fdiv_rn(__fsub_rn(gcy, cy), h), 0.1f);
            d1 = __fdiv_rn(__fdiv_rn(__fsub_rn(gcx, cx), w), 0.1f);
            d2 = __fdiv_rn((float)log((double)__fdiv_rn(gh, h)), 0.2f);
            d3 = __fdiv_rn((float)log((double)__fdiv_rn(gw, w)), 0.2f);
            c = (float)s_cls[ga];
        }
        d_gt_assign[b][t] = ga;
        d_pos_roi[b][t][0] = r0; d_pos_roi[b][t][1] = r1;
        d_pos_roi[b][t][2] = r2; d_pos_roi[b][t][3] = r3;
        rois_out[t * 4 + 0] = r0; rois_out[t * 4 + 1] = r1;
        rois_out[t * 4 + 2] = r2; rois_out[t * 4 + 3] = r3;
        cls_out[t] = c;
        del_out[t * 4 + 0] = d0; del_out[t * 4 + 1] = d1;
        del_out[t * 4 + 2] = d2; del_out[t * 4 + 3] = d3;
    } else if (t < TROIS) {
        int j = t - PCAP;
        float r0 = 0, r1 = 0, r2 = 0, r3 = 0;
        if (j < nn) {
            int n = s_neg_idx[j];
            const float* pp = props + ((size_t)b * NP + n) * 4;
            r0 = pp[0]; r1 = pp[1]; r2 = pp[2]; r3 = pp[3];
        }
        rois_out[t * 4 + 0] = r0; rois_out[t * 4 + 1] = r1;
        rois_out[t * 4 + 2] = r2; rois_out[t * 4 + 3] = r3;
        cls_out[t] = 0.0f;
        del_out[t * 4 + 0] = 0.0f; del_out[t * 4 + 1] = 0.0f;
        del_out[t * 4 + 2] = 0.0f; del_out[t * 4 + 3] = 0.0f;
    }
}

// ---------------------------------------------------------------------------
// Kernel 2: mask targets. TWO blocks per (image, roi-slot), 392 threads each.
// DRAM-bound scattered gather; at the [H,W,G]-layout structural floor.
// ---------------------------------------------------------------------------
#define MBLK 392
__device__ __forceinline__ float load_mask_val(const void* masks, int kind, size_t idx) {
    if (kind == 0) return (float)__ldg((const unsigned char*)masks + idx);
    if (kind == 1) return (float)__ldg((const int*)masks + idx);
    return __ldg((const float*)masks + idx);
}

__global__ void __launch_bounds__(MBLK) k_masks(const void* __restrict__ masks,
                                                float* __restrict__ out) {
    int part = blockIdx.x & 1;
    int sb   = blockIdx.x >> 1;
    int slot = sb % TROIS;
    int b    = sb / TROIS;
    int p    = part * MBLK + threadIdx.x;     // 0..783
    float* mout = out + OFF_MASK + ((size_t)(b * TROIS + slot)) * MPIX;

    int np = d_num_pos[b];
    if (slot >= np || slot >= PCAP) {
        mout[p] = 0.0f;
        return;
    }
    int kind = d_mask_kind;
    float y1 = d_pos_roi[b][slot][0];
    float x1 = d_pos_roi[b][slot][1];
    float y2 = d_pos_roi[b][slot][2];
    float x2 = d_pos_roi[b][slot][3];
    int g = d_gt_assign[b][slot];
    float dy = __fsub_rn(y2, y1);
    float dx = __fsub_rn(x2, x1);

    int i = p / MS2;
    int j = p % MS2;
    // ys = (y1 + (y2-y1)*i/27) * 1023  — exact jnp op order, IEEE rn
    float ys = __fmul_rn(__fadd_rn(y1, __fdiv_rn(__fmul_rn(dy, (float)i), 27.0f)), 1023.0f);
    float xs = __fmul_rn(__fadd_rn(x1, __fdiv_rn(__fmul_rn(dx, (float)j), 27.0f)), 1023.0f);

    float y0f = fminf(fmaxf(floorf(ys), 0.0f), 1023.0f);
    float x0f = fminf(fmaxf(floorf(xs), 0.0f), 1023.0f);
    int y0 = (int)y0f;
    int x0 = (int)x0f;
    int y1i = (int)fminf(__fadd_rn(y0f, 1.0f), 1023.0f);
    int x1i = (int)fminf(__fadd_rn(x0f, 1.0f), 1023.0f);
    float wy = __fsub_rn(ys, y0f);
    float wx = __fsub_rn(xs, x0f);
    float oy = __fsub_rn(1.0f, wy);
    float ox = __fsub_rn(1.0f, wx);

    size_t base_b = (size_t)b * MH;
    size_t row0 = (base_b + (size_t)y0)  * MW;
    size_t row1 = (base_b + (size_t)y1i) * MW;
    float m00 = load_mask_val(masks, kind, (row0 + x0)  * NG + g);
    float m01 = load_mask_val(masks, kind, (row0 + x1i) * NG + g);
    float m10 = load_mask_val(masks, kind, (row1 + x0)  * NG + g);
    float m11 = load_mask_val(masks, kind, (row1 + x1i) * NG + g);

    float t0 = __fmul_rn(__fmul_rn(m00, oy), ox);
    float t1 = __fmul_rn(__fmul_rn(m01, oy), wx);
    float t2 = __fmul_rn(__fmul_rn(m10, wy), ox);
    float t3 = __fmul_rn(__fmul_rn(m11, wy), wx);
    float val = __fadd_rn(__fadd_rn(__fadd_rn(t0, t1), t2), t3);
    mout[p] = rintf(val);   // round-half-even, matches jnp.round
}

extern "C" void kernel_launch(void* const* d_in, const int* in_sizes, int n_in,
                              void* d_out, int out_size) {
    const float* props = (const float*)d_in[0];
    const int*   gtc   = (const int*)d_in[1];
    const float* gtb   = (const float*)d_in[2];
    const void*  masks = d_in[3];
    float* out = (float*)d_out;

    k_flags_select<<<BB * CHUNKS + 1, FBLK>>>(props, gtc, gtb,
                                              (const unsigned int*)masks, out);
    k_masks<<<BB * TROIS * 2, MBLK>>>(masks, out);
}